// round 16
// baseline (speedup 1.0000x reference)
#include <cuda_runtime.h>
#include <cuda_fp16.h>
#include <math.h>
#include <stdint.h>

// Problem constants
#define BATCH 4
#define SLEN  2048
#define EMB   1024
#define QKVF  3072

// ---------------------------------------------------------------------------
// Device scratch (allocation-free rule: __device__ globals)
// ---------------------------------------------------------------------------
__device__ __align__(256) __half g_Xf [(size_t)BATCH*SLEN*EMB];   // X fp16
__device__ __align__(256) __half g_Wqf[(size_t)QKVF*EMB];         // W_qkv fp16
__device__ __align__(256) __half g_Wof[(size_t)EMB*EMB];          // W_out fp16
__device__ __align__(256) __half g_qf [(size_t)BATCH*SLEN*EMB];   // q fp16
__device__ __align__(256) __half g_kf [(size_t)BATCH*SLEN*EMB];   // k fp16
__device__ __align__(256) __half g_vtf[(size_t)BATCH*EMB*SLEN];   // V^T fp16 [b,e,s]
__device__ __align__(256) __half g_E  [(size_t)BATCH*SLEN*SLEN];  // exp(s)*mask fp16
__device__ __align__(256) float  g_rs [(size_t)BATCH*SLEN];       // 1/rowsum
__device__ __align__(256) __half g_cf [(size_t)BATCH*SLEN*EMB];   // ctx fp16

// ---------------------------------------------------------------------------
// PTX helpers (sm_80+ only — tcgen05 rejected by compute_103 PTX target)
// ---------------------------------------------------------------------------
__device__ __forceinline__ uint32_t smem_u32(const void* p) {
    uint32_t a;
    asm("{ .reg .u64 t; cvta.to.shared.u64 t, %1; cvt.u32.u64 %0, t; }"
        : "=r"(a) : "l"(p));
    return a;
}
#define CP16(d, s)   asm volatile("cp.async.cg.shared.global [%0], [%1], 16;" :: "r"(d), "l"(s))
#define CP_COMMIT()  asm volatile("cp.async.commit_group;" ::: "memory")
#define CP_WAIT1()   asm volatile("cp.async.wait_group 1;" ::: "memory")
#define CP_WAIT0()   asm volatile("cp.async.wait_group 0;" ::: "memory")

__device__ __forceinline__ void ldsm4(uint32_t* r, uint32_t addr) {
    asm volatile("ldmatrix.sync.aligned.m8n8.x4.shared.b16 {%0,%1,%2,%3}, [%4];"
        : "=r"(r[0]), "=r"(r[1]), "=r"(r[2]), "=r"(r[3]) : "r"(addr));
}
__device__ __forceinline__ void hmma16816(float* d, const uint32_t* a, const uint32_t* b) {
    asm volatile("mma.sync.aligned.m16n8k16.row.col.f32.f16.f16.f32 "
        "{%0,%1,%2,%3}, {%4,%5,%6,%7}, {%8,%9}, {%0,%1,%2,%3};"
        : "+f"(d[0]), "+f"(d[1]), "+f"(d[2]), "+f"(d[3])
        : "r"(a[0]), "r"(a[1]), "r"(a[2]), "r"(a[3]), "r"(b[0]), "r"(b[1]));
}

// ---- pure fp16 tiling: CTA 128x128, BK=64, 8 warps (2x4), 2 CTAs/SM ----
// 3-stage cp.async pipeline (2 loads in flight).
#define HROWB   144
#define HTILE   (128 * HROWB)            // 18432 B
#define HSTAGE  (2 * HTILE)              // B tile + A tile = 36864 B
#define NSTAGES 3
#define HG_SMEM (NSTAGES * HSTAGE + 128) // 110720 B -> 2 CTAs/SM

// ===========================================================================
// hgemm (pure fp16, 1 MMA):  D[m,n] = alpha*sum_k A[m,k]B[n,k] (+bias)
// MODE 0 (qkv):    A=X, B=Wq; bias; emit q fp16 / k fp16 / V^T fp16 (transposed)
// MODE 1 (scores): A=q, B=k; epilogue: E = mask ? exp(s/32) : 0, fp16 out
// MODE 2 (ctx):    A=E, B=V^T; epilogue scales by 1/rowsum; ctx fp16 out
// MODE 3 (proj):   A=ctx, B=Wo; bias; fp32 out
// ===========================================================================
template<int MODE>
__global__ void __launch_bounds__(256, 2)
hgemm_k(const __half* __restrict__ A, const __half* __restrict__ B,
        size_t sA, int ldA, size_t sB, int ldB, int K, float alpha,
        float* __restrict__ outF, size_t sF, int ldF,
        __half* __restrict__ o0, __half* __restrict__ o1,
        __half* __restrict__ o3,
        const float* __restrict__ bias,
        const int* __restrict__ mask,
        const float* __restrict__ rowscale)
{
    extern __shared__ char dsm[];
    const uint32_t sb0 = smem_u32(dsm);
    const uint32_t SB  = (sb0 + 127u) & ~127u;
    float* stg = (float*)(dsm + (SB - sb0));

    const int tid  = threadIdx.x;
    const int wid  = tid >> 5, lane = tid & 31;
    const int wm   = wid >> 2, wn = wid & 3;    // warp 64x32
    const int bx = blockIdx.x, by = blockIdx.y, z = blockIdx.z;

    const char* bB = (const char*)(B + (size_t)z * sB + (size_t)bx * 128 * ldB);
    const char* bA = (const char*)(A + (size_t)z * sA + (size_t)by * 128 * ldA);
    const size_t strB = (size_t)ldB * 2, strA = (size_t)ldA * 2;

    auto load_chunk = [&](int c, int s) {
        const uint32_t stb = SB + (uint32_t)s * HSTAGE;
        #pragma unroll
        for (int i = 0; i < 8; i++) {
            const int id = i * 256 + tid;       // 0..2047
            const int t  = id >> 10;            // 0 = B tile, 1 = A tile
            const int u  = id & 1023;
            const int r  = u >> 3;
            const int c16 = u & 7;
            const char* base = t ? bA : bB;
            const size_t str = t ? strA : strB;
            const char* src = base + (size_t)r * str + (size_t)c * 128 + (size_t)c16 * 16;
            const uint32_t dst = stb + (uint32_t)t * HTILE + (uint32_t)(r * HROWB + c16 * 16);
            CP16(dst, src);
        }
        CP_COMMIT();
    };

    float d[4][4][4];
    #pragma unroll
    for (int a = 0; a < 4; a++)
        #pragma unroll
        for (int b = 0; b < 4; b++)
            #pragma unroll
            for (int e = 0; e < 4; e++) d[a][b][e] = 0.0f;

    const int NC = K >> 6;
    load_chunk(0, 0);
    if (NC > 1) load_chunk(1, 1);

    const uint32_t offA = (uint32_t)((wm * 64 + (lane & 7) + ((lane >> 3) & 1) * 8) * HROWB
                                     + ((lane >> 4) & 1) * 16);
    const uint32_t offB = (uint32_t)((wn * 32 + ((lane >> 4) & 1) * 8 + (lane & 7)) * HROWB
                                     + ((lane >> 3) & 1) * 16);

    int stage = 0;
    for (int c = 0; c < NC; c++) {
        if (c + 1 < NC) CP_WAIT1(); else CP_WAIT0();
        __syncthreads();
        if (c + 2 < NC) {
            int s2 = stage + 2; if (s2 >= NSTAGES) s2 -= NSTAGES;
            load_chunk(c + 2, s2);
        }

        const uint32_t stb = SB + (uint32_t)stage * HSTAGE;
        const uint32_t B_s = stb, A_s = stb + HTILE;

        #pragma unroll
        for (int kk = 0; kk < 4; kk++) {
            uint32_t bq[8];
            ldsm4(&bq[0], B_s + offB + (uint32_t)(kk * 32));
            ldsm4(&bq[4], B_s + offB + (uint32_t)(16 * HROWB + kk * 32));
            #pragma unroll
            for (int mt = 0; mt < 4; mt++) {
                uint32_t a[4];
                ldsm4(a, A_s + offA + (uint32_t)(mt * 16 * HROWB + kk * 32));
                #pragma unroll
                for (int nt = 0; nt < 4; nt++)
                    hmma16816(d[mt][nt], a, &bq[nt * 2]);
            }
        }
        if (++stage == NSTAGES) stage = 0;
    }
    __syncthreads();

    // ---- accumulators -> smem staging (alpha, optional bias, MODE2 rowscale) ----
    #pragma unroll
    for (int mt = 0; mt < 4; mt++) {
        #pragma unroll
        for (int nt = 0; nt < 4; nt++) {
            const int r0 = wm * 64 + mt * 16 + (lane >> 2);
            const int c0 = wn * 32 + nt * 8 + (lane & 3) * 2;
            #pragma unroll
            for (int h = 0; h < 2; h++) {
                const int row = r0 + h * 8;
                float sc = alpha;
                if (MODE == 2)
                    sc = rowscale[(size_t)z * SLEN + by * 128 + row];
                float v0 = d[mt][nt][h * 2 + 0] * sc;
                float v1 = d[mt][nt][h * 2 + 1] * sc;
                if (MODE == 0 || MODE == 3) {
                    v0 += bias[bx * 128 + c0];
                    v1 += bias[bx * 128 + c0 + 1];
                }
                *(float2*)&stg[row * 132 + c0] = make_float2(v0, v1);
            }
        }
    }
    __syncthreads();

    // ---- MODE-specific writers ----
    if (MODE == 3) {
        const int row = tid >> 1, h = tid & 1;
        float* dst = outF + ((size_t)by * 128 + row) * ldF
                   + (size_t)bx * 128 + h * 64;
        #pragma unroll
        for (int q = 0; q < 16; q++) {
            float4 v;
            v.x = stg[row * 132 + h * 64 + q * 4 + 0];
            v.y = stg[row * 132 + h * 64 + q * 4 + 1];
            v.z = stg[row * 132 + h * 64 + q * 4 + 2];
            v.w = stg[row * 132 + h * 64 + q * 4 + 3];
            ((float4*)dst)[q] = v;
        }
    } else if (MODE == 1) {
        // fused masked exp: E = mask ? exp(s) : 0, fp16 out (o0)
        const int row = tid >> 1, h = tid & 1;
        const size_t rbase = (size_t)z * SLEN * SLEN
                           + ((size_t)by * 128 + row) * SLEN + bx * 128 + h * 64;
        const int4* mrow = (const int4*)(mask + rbase);
        __half* erow = o0 + rbase;
        #pragma unroll
        for (int q = 0; q < 16; q++) {
            const int4 m = mrow[q];
            union { __half h4[4]; uint2 u; } U;
            U.h4[0] = __float2half(m.x ? __expf(stg[row * 132 + h * 64 + q * 4 + 0]) : 0.0f);
            U.h4[1] = __float2half(m.y ? __expf(stg[row * 132 + h * 64 + q * 4 + 1]) : 0.0f);
            U.h4[2] = __float2half(m.z ? __expf(stg[row * 132 + h * 64 + q * 4 + 2]) : 0.0f);
            U.h4[3] = __float2half(m.w ? __expf(stg[row * 132 + h * 64 + q * 4 + 3]) : 0.0f);
            *(uint2*)(erow + q * 4) = U.u;
        }
    } else if (MODE == 2) {
        // ctx -> single fp16 (row-major), o0
        #pragma unroll 1
        for (int cb = 0; cb < 4; cb++) {
            #pragma unroll 1
            for (int it = 0; it < 2; it++) {
                const int row = it * 64 + (tid >> 2);
                const int qq  = tid & 3;
                const int col = cb * 32 + qq * 8;
                const size_t rg = (size_t)z * SLEN + (size_t)by * 128 + row;
                union { __half h4[8]; uint4 v; } U;
                #pragma unroll
                for (int i = 0; i < 8; i++)
                    U.h4[i] = __float2half(stg[row * 132 + col + i]);
                *(uint4*)(o0 + rg * 1024 + bx * 128 + col) = U.v;
            }
        }
    } else if (MODE == 0 && bx < 16) {      // q (bx<8 -> o0) / k (bx<16 -> o1)
        __half* O = (bx < 8) ? o0 : o1;
        const int cbase = (bx & 7) * 128;
        #pragma unroll 1
        for (int cb = 0; cb < 4; cb++) {
            #pragma unroll 1
            for (int it = 0; it < 2; it++) {
                const int row = it * 64 + (tid >> 2);
                const int qq  = tid & 3;
                const int col = cb * 32 + qq * 8;
                const size_t rg = (size_t)by * 128 + row;
                union { __half h4[8]; uint4 v; } U;
                #pragma unroll
                for (int i = 0; i < 8; i++)
                    U.h4[i] = __float2half(stg[row * 132 + col + i]);
                *(uint4*)(O + rg * 1024 + cbase + col) = U.v;
            }
        }
    } else if (MODE == 0) {                 // V^T fp16, transposed (o3)
        const int j  = tid >> 3;
        const int rs = tid & 7;
        const int bidx = by >> 4;
        const int s0 = (by * 128) & 2047;
        #pragma unroll 1
        for (int cb = 0; cb < 4; cb++) {
            const int col = cb * 32 + j;
            const int colE = (bx - 16) * 128 + col;
            union { __half h4[16]; uint4 v[2]; } U;
            #pragma unroll
            for (int i = 0; i < 16; i++)
                U.h4[i] = __float2half(stg[(rs * 16 + i) * 132 + col]);
            const size_t off = ((size_t)bidx * 1024 + colE) * 2048 + s0 + rs * 16;
            *(uint4*)(o3 + off)     = U.v[0];
            *(uint4*)(o3 + off + 8) = U.v[1];
        }
    }
}

// ---------------------------------------------------------------------------
// Row-sum of E: one block per row; writes 1/sum.
// ---------------------------------------------------------------------------
__global__ void __launch_bounds__(256)
rowsum_k(const __half* __restrict__ E, float* __restrict__ rs)
{
    const size_t row = blockIdx.x;
    const uint4* e4 = (const uint4*)(E + row * (size_t)SLEN);  // 8 halves per uint4
    const int tid = threadIdx.x;

    const uint4 u = e4[tid];                 // 256 threads x 8 halves = 2048
    const __half2* h2 = (const __half2*)&u;
    float lsum = 0.0f;
    #pragma unroll
    for (int i = 0; i < 4; i++) {
        const float2 f = __half22float2(h2[i]);
        lsum += f.x + f.y;
    }
    __shared__ float ssum[8];
    #pragma unroll
    for (int o = 16; o > 0; o >>= 1)
        lsum += __shfl_xor_sync(0xffffffffu, lsum, o);
    if ((tid & 31) == 0) ssum[tid >> 5] = lsum;
    __syncthreads();
    if (tid == 0) {
        const float tot = (ssum[0] + ssum[1]) + (ssum[2] + ssum[3])
                        + (ssum[4] + ssum[5]) + (ssum[6] + ssum[7]);
        rs[row] = 1.0f / tot;
    }
}

// ---------------------------------------------------------------------------
// Input conversion: X, W_qkv, W_out -> single fp16, ONE launch
// ---------------------------------------------------------------------------
__global__ void conv_all(const float4* __restrict__ X,  __half* __restrict__ Xf, int n1,
                         const float4* __restrict__ Wq, __half* __restrict__ Wqf, int n2,
                         const float4* __restrict__ Wo, __half* __restrict__ Wof, int n3)
{
    int i = blockIdx.x * 256 + threadIdx.x;
    const float4* src; __half* dst;
    if (i < n1)            { src = X;  dst = Xf;  }
    else if (i < n1 + n2)  { src = Wq; dst = Wqf; i -= n1; }
    else if (i < n1+n2+n3) { src = Wo; dst = Wof; i -= n1 + n2; }
    else return;
    const float4 v = src[i];
    union { __half h[4]; uint2 u; } U;
    U.h[0] = __float2half(v.x); U.h[1] = __float2half(v.y);
    U.h[2] = __float2half(v.z); U.h[3] = __float2half(v.w);
    *(uint2*)(dst + (size_t)i * 4) = U.u;
}

// ---------------------------------------------------------------------------
extern "C" void kernel_launch(void* const* d_in, const int* in_sizes, int n_in,
                              void* d_out, int out_size)
{
    const float* X     = (const float*)d_in[0];
    const int*   mask  = (const int*)  d_in[1];
    const float* W_qkv = (const float*)d_in[2];
    const float* b_qkv = (const float*)d_in[3];
    const float* W_out = (const float*)d_in[4];
    const float* b_out = (const float*)d_in[5];
    float*       out   = (float*)d_out;

    __half *Xf, *Wqf, *Wof, *qf, *kf, *vtf, *E, *cf;
    float *rs;
    cudaGetSymbolAddress((void**)&Xf,   g_Xf);
    cudaGetSymbolAddress((void**)&Wqf,  g_Wqf);
    cudaGetSymbolAddress((void**)&Wof,  g_Wof);
    cudaGetSymbolAddress((void**)&qf,   g_qf);
    cudaGetSymbolAddress((void**)&kf,   g_kf);
    cudaGetSymbolAddress((void**)&vtf,  g_vtf);
    cudaGetSymbolAddress((void**)&E,    g_E);
    cudaGetSymbolAddress((void**)&rs,   g_rs);
    cudaGetSymbolAddress((void**)&cf,   g_cf);

    cudaFuncSetAttribute(hgemm_k<0>, cudaFuncAttributeMaxDynamicSharedMemorySize, HG_SMEM);
    cudaFuncSetAttribute(hgemm_k<1>, cudaFuncAttributeMaxDynamicSharedMemorySize, HG_SMEM);
    cudaFuncSetAttribute(hgemm_k<2>, cudaFuncAttributeMaxDynamicSharedMemorySize, HG_SMEM);
    cudaFuncSetAttribute(hgemm_k<3>, cudaFuncAttributeMaxDynamicSharedMemorySize, HG_SMEM);

    // Convert inputs (single launch)
    {
        const int n1 = BATCH*SLEN*EMB/4, n2 = QKVF*EMB/4, n3 = EMB*EMB/4;
        conv_all<<<(n1 + n2 + n3 + 255)/256, 256>>>(
            (const float4*)X, Xf, n1,
            (const float4*)W_qkv, Wqf, n2,
            (const float4*)W_out, Wof, n3);
    }

    // 1) qkv = X @ W_qkv^T + b  -> q fp16, k fp16, V^T fp16
    hgemm_k<0><<<dim3(QKVF/128, (BATCH*SLEN)/128), 256, HG_SMEM>>>(
        Xf, Wqf, 0, EMB, 0, EMB, EMB, 1.0f,
        nullptr, 0, 0, qf, kf, vtf, b_qkv, nullptr, nullptr);

    // 2) E = mask ? exp(Q@K^T / 32) : 0   (fp16 out, fused epilogue)
    hgemm_k<1><<<dim3(SLEN/128, SLEN/128, BATCH), 256, HG_SMEM>>>(
        qf, kf, (size_t)SLEN*EMB, EMB, (size_t)SLEN*EMB, EMB, EMB, 0.03125f,
        nullptr, 0, 0, E, nullptr, nullptr, nullptr, mask, nullptr);

    // 3) rowsum -> 1/sum per row
    rowsum_k<<<BATCH*SLEN, 256>>>(E, rs);

    // 4) ctx = (E @ V) * (1/rowsum)  -> ctx fp16
    hgemm_k<2><<<dim3(EMB/128, SLEN/128, BATCH), 256, HG_SMEM>>>(
        E, vtf, (size_t)SLEN*SLEN, SLEN, (size_t)EMB*SLEN, SLEN, SLEN, 1.0f,
        nullptr, 0, 0, cf, nullptr, nullptr, nullptr, nullptr, rs);

    // 5) out = ctx @ W_out^T + b  (fp32 out)
    hgemm_k<3><<<dim3(EMB/128, (BATCH*SLEN)/128), 256, HG_SMEM>>>(
        cf, Wof, 0, EMB, 0, EMB, EMB, 1.0f,
        out, 0, EMB, nullptr, nullptr, nullptr, b_out, nullptr, nullptr);
}

// round 17
// speedup vs baseline: 1.0070x; 1.0070x over previous
#include <cuda_runtime.h>
#include <cuda_fp16.h>
#include <math.h>
#include <stdint.h>

// Problem constants
#define BATCH 4
#define SLEN  2048
#define EMB   1024
#define QKVF  3072

// ---------------------------------------------------------------------------
// Device scratch (allocation-free rule: __device__ globals)
// ---------------------------------------------------------------------------
__device__ __align__(256) __half g_Xf [(size_t)BATCH*SLEN*EMB];   // X fp16
__device__ __align__(256) __half g_Wqf[(size_t)QKVF*EMB];         // W_qkv fp16
__device__ __align__(256) __half g_Wof[(size_t)EMB*EMB];          // W_out fp16
__device__ __align__(256) __half g_qf [(size_t)BATCH*SLEN*EMB];   // q fp16
__device__ __align__(256) __half g_kf [(size_t)BATCH*SLEN*EMB];   // k fp16
__device__ __align__(256) __half g_vtf[(size_t)BATCH*EMB*SLEN];   // V^T fp16 [b,e,s]
__device__ __align__(256) __half g_E  [(size_t)BATCH*SLEN*SLEN];  // exp(s)*mask fp16
__device__ __align__(256) float  g_rs [(size_t)BATCH*SLEN];       // rowsum (atomic)
__device__ __align__(256) __half g_cf [(size_t)BATCH*SLEN*EMB];   // ctx fp16

// ---------------------------------------------------------------------------
// PTX helpers (sm_80+ only — tcgen05 rejected by compute_103 PTX target)
// ---------------------------------------------------------------------------
__device__ __forceinline__ uint32_t smem_u32(const void* p) {
    uint32_t a;
    asm("{ .reg .u64 t; cvta.to.shared.u64 t, %1; cvt.u32.u64 %0, t; }"
        : "=r"(a) : "l"(p));
    return a;
}
#define CP16(d, s)   asm volatile("cp.async.cg.shared.global [%0], [%1], 16;" :: "r"(d), "l"(s))
#define CP_COMMIT()  asm volatile("cp.async.commit_group;" ::: "memory")
#define CP_WAIT1()   asm volatile("cp.async.wait_group 1;" ::: "memory")
#define CP_WAIT0()   asm volatile("cp.async.wait_group 0;" ::: "memory")

__device__ __forceinline__ void ldsm4(uint32_t* r, uint32_t addr) {
    asm volatile("ldmatrix.sync.aligned.m8n8.x4.shared.b16 {%0,%1,%2,%3}, [%4];"
        : "=r"(r[0]), "=r"(r[1]), "=r"(r[2]), "=r"(r[3]) : "r"(addr));
}
__device__ __forceinline__ void hmma16816(float* d, const uint32_t* a, const uint32_t* b) {
    asm volatile("mma.sync.aligned.m16n8k16.row.col.f32.f16.f16.f32 "
        "{%0,%1,%2,%3}, {%4,%5,%6,%7}, {%8,%9}, {%0,%1,%2,%3};"
        : "+f"(d[0]), "+f"(d[1]), "+f"(d[2]), "+f"(d[3])
        : "r"(a[0]), "r"(a[1]), "r"(a[2]), "r"(a[3]), "r"(b[0]), "r"(b[1]));
}

// ---- pure fp16 tiling: CTA 128x128, BK=64, 8 warps (2x4), 2 CTAs/SM ----
// 3-stage cp.async pipeline (2 loads in flight).
#define HROWB   144
#define HTILE   (128 * HROWB)            // 18432 B
#define HSTAGE  (2 * HTILE)              // B tile + A tile = 36864 B
#define NSTAGES 3
#define HG_SMEM (NSTAGES * HSTAGE + 128) // 110720 B -> 2 CTAs/SM

// ===========================================================================
// hgemm (pure fp16, 1 MMA):  D[m,n] = alpha*sum_k A[m,k]B[n,k] (+bias)
// MODE 0 (qkv):    A=X, B=Wq; bias; emit q fp16 / k fp16 / V^T fp16 (transposed)
// MODE 1 (scores): A=q, B=k; epilogue: E = mask ? exp(s/32) : 0, fp16 out;
//                  per-row partial sums atomically added to g_rs.
// MODE 2 (ctx):    A=E, B=V^T; epilogue scales by 1/rowsum; ctx fp16 out
// MODE 3 (proj):   A=ctx, B=Wo; bias; fp32 out
// ===========================================================================
template<int MODE>
__global__ void __launch_bounds__(256, 2)
hgemm_k(const __half* __restrict__ A, const __half* __restrict__ B,
        size_t sA, int ldA, size_t sB, int ldB, int K, float alpha,
        float* __restrict__ outF, size_t sF, int ldF,
        __half* __restrict__ o0, __half* __restrict__ o1,
        __half* __restrict__ o3,
        const float* __restrict__ bias,
        const int* __restrict__ mask,
        float* __restrict__ rowsum)
{
    extern __shared__ char dsm[];
    const uint32_t sb0 = smem_u32(dsm);
    const uint32_t SB  = (sb0 + 127u) & ~127u;
    float* stg = (float*)(dsm + (SB - sb0));

    const int tid  = threadIdx.x;
    const int wid  = tid >> 5, lane = tid & 31;
    const int wm   = wid >> 2, wn = wid & 3;    // warp 64x32
    const int bx = blockIdx.x, by = blockIdx.y, z = blockIdx.z;

    const char* bB = (const char*)(B + (size_t)z * sB + (size_t)bx * 128 * ldB);
    const char* bA = (const char*)(A + (size_t)z * sA + (size_t)by * 128 * ldA);
    const size_t strB = (size_t)ldB * 2, strA = (size_t)ldA * 2;

    auto load_chunk = [&](int c, int s) {
        const uint32_t stb = SB + (uint32_t)s * HSTAGE;
        #pragma unroll
        for (int i = 0; i < 8; i++) {
            const int id = i * 256 + tid;       // 0..2047
            const int t  = id >> 10;            // 0 = B tile, 1 = A tile
            const int u  = id & 1023;
            const int r  = u >> 3;
            const int c16 = u & 7;
            const char* base = t ? bA : bB;
            const size_t str = t ? strA : strB;
            const char* src = base + (size_t)r * str + (size_t)c * 128 + (size_t)c16 * 16;
            const uint32_t dst = stb + (uint32_t)t * HTILE + (uint32_t)(r * HROWB + c16 * 16);
            CP16(dst, src);
        }
        CP_COMMIT();
    };

    float d[4][4][4];
    #pragma unroll
    for (int a = 0; a < 4; a++)
        #pragma unroll
        for (int b = 0; b < 4; b++)
            #pragma unroll
            for (int e = 0; e < 4; e++) d[a][b][e] = 0.0f;

    const int NC = K >> 6;
    load_chunk(0, 0);
    if (NC > 1) load_chunk(1, 1);

    const uint32_t offA = (uint32_t)((wm * 64 + (lane & 7) + ((lane >> 3) & 1) * 8) * HROWB
                                     + ((lane >> 4) & 1) * 16);
    const uint32_t offB = (uint32_t)((wn * 32 + ((lane >> 4) & 1) * 8 + (lane & 7)) * HROWB
                                     + ((lane >> 3) & 1) * 16);

    int stage = 0;
    for (int c = 0; c < NC; c++) {
        if (c + 1 < NC) CP_WAIT1(); else CP_WAIT0();
        __syncthreads();
        if (c + 2 < NC) {
            int s2 = stage + 2; if (s2 >= NSTAGES) s2 -= NSTAGES;
            load_chunk(c + 2, s2);
        }

        const uint32_t stb = SB + (uint32_t)stage * HSTAGE;
        const uint32_t B_s = stb, A_s = stb + HTILE;

        #pragma unroll
        for (int kk = 0; kk < 4; kk++) {
            uint32_t bq[8];
            ldsm4(&bq[0], B_s + offB + (uint32_t)(kk * 32));
            ldsm4(&bq[4], B_s + offB + (uint32_t)(16 * HROWB + kk * 32));
            #pragma unroll
            for (int mt = 0; mt < 4; mt++) {
                uint32_t a[4];
                ldsm4(a, A_s + offA + (uint32_t)(mt * 16 * HROWB + kk * 32));
                #pragma unroll
                for (int nt = 0; nt < 4; nt++)
                    hmma16816(d[mt][nt], a, &bq[nt * 2]);
            }
        }
        if (++stage == NSTAGES) stage = 0;
    }
    __syncthreads();

    // ---- accumulators -> smem staging (alpha, optional bias, MODE2 rowscale) ----
    #pragma unroll
    for (int mt = 0; mt < 4; mt++) {
        #pragma unroll
        for (int nt = 0; nt < 4; nt++) {
            const int r0 = wm * 64 + mt * 16 + (lane >> 2);
            const int c0 = wn * 32 + nt * 8 + (lane & 3) * 2;
            #pragma unroll
            for (int h = 0; h < 2; h++) {
                const int row = r0 + h * 8;
                float sc = alpha;
                if (MODE == 2)
                    sc = 1.0f / rowsum[(size_t)z * SLEN + by * 128 + row];
                float v0 = d[mt][nt][h * 2 + 0] * sc;
                float v1 = d[mt][nt][h * 2 + 1] * sc;
                if (MODE == 0 || MODE == 3) {
                    v0 += bias[bx * 128 + c0];
                    v1 += bias[bx * 128 + c0 + 1];
                }
                *(float2*)&stg[row * 132 + c0] = make_float2(v0, v1);
            }
        }
    }
    __syncthreads();

    // ---- MODE-specific writers ----
    if (MODE == 3) {
        const int row = tid >> 1, h = tid & 1;
        float* dst = outF + ((size_t)by * 128 + row) * ldF
                   + (size_t)bx * 128 + h * 64;
        #pragma unroll
        for (int q = 0; q < 16; q++) {
            float4 v;
            v.x = stg[row * 132 + h * 64 + q * 4 + 0];
            v.y = stg[row * 132 + h * 64 + q * 4 + 1];
            v.z = stg[row * 132 + h * 64 + q * 4 + 2];
            v.w = stg[row * 132 + h * 64 + q * 4 + 3];
            ((float4*)dst)[q] = v;
        }
    } else if (MODE == 1) {
        // fused masked exp + partial row-sum: E = mask ? exp(s) : 0 (fp16),
        // row partials atomically accumulated into rowsum[].
        const int row = tid >> 1, h = tid & 1;
        const size_t rbase = (size_t)z * SLEN * SLEN
                           + ((size_t)by * 128 + row) * SLEN + bx * 128 + h * 64;
        const int4* mrow = (const int4*)(mask + rbase);
        __half* erow = o0 + rbase;
        float rsum = 0.0f;
        #pragma unroll
        for (int q = 0; q < 16; q++) {
            const int4 m = mrow[q];
            float e0 = m.x ? __expf(stg[row * 132 + h * 64 + q * 4 + 0]) : 0.0f;
            float e1 = m.y ? __expf(stg[row * 132 + h * 64 + q * 4 + 1]) : 0.0f;
            float e2 = m.z ? __expf(stg[row * 132 + h * 64 + q * 4 + 2]) : 0.0f;
            float e3 = m.w ? __expf(stg[row * 132 + h * 64 + q * 4 + 3]) : 0.0f;
            rsum += (e0 + e1) + (e2 + e3);
            union { __half h4[4]; uint2 u; } U;
            U.h4[0] = __float2half(e0);
            U.h4[1] = __float2half(e1);
            U.h4[2] = __float2half(e2);
            U.h4[3] = __float2half(e3);
            *(uint2*)(erow + q * 4) = U.u;
        }
        // combine the two halves of the row (tid and tid^1 are adjacent lanes)
        rsum += __shfl_xor_sync(0xffffffffu, rsum, 1);
        if (h == 0)
            atomicAdd(rowsum + (size_t)z * SLEN + by * 128 + row, rsum);
    } else if (MODE == 2) {
        // ctx -> single fp16 (row-major), o0
        #pragma unroll 1
        for (int cb = 0; cb < 4; cb++) {
            #pragma unroll 1
            for (int it = 0; it < 2; it++) {
                const int row = it * 64 + (tid >> 2);
                const int qq  = tid & 3;
                const int col = cb * 32 + qq * 8;
                const size_t rg = (size_t)z * SLEN + (size_t)by * 128 + row;
                union { __half h4[8]; uint4 v; } U;
                #pragma unroll
                for (int i = 0; i < 8; i++)
                    U.h4[i] = __float2half(stg[row * 132 + col + i]);
                *(uint4*)(o0 + rg * 1024 + bx * 128 + col) = U.v;
            }
        }
    } else if (MODE == 0 && bx < 16) {      // q (bx<8 -> o0) / k (bx<16 -> o1)
        __half* O = (bx < 8) ? o0 : o1;
        const int cbase = (bx & 7) * 128;
        #pragma unroll 1
        for (int cb = 0; cb < 4; cb++) {
            #pragma unroll 1
            for (int it = 0; it < 2; it++) {
                const int row = it * 64 + (tid >> 2);
                const int qq  = tid & 3;
                const int col = cb * 32 + qq * 8;
                const size_t rg = (size_t)by * 128 + row;
                union { __half h4[8]; uint4 v; } U;
                #pragma unroll
                for (int i = 0; i < 8; i++)
                    U.h4[i] = __float2half(stg[row * 132 + col + i]);
                *(uint4*)(O + rg * 1024 + cbase + col) = U.v;
            }
        }
    } else if (MODE == 0) {                 // V^T fp16, transposed (o3)
        const int j  = tid >> 3;
        const int rs = tid & 7;
        const int bidx = by >> 4;
        const int s0 = (by * 128) & 2047;
        #pragma unroll 1
        for (int cb = 0; cb < 4; cb++) {
            const int col = cb * 32 + j;
            const int colE = (bx - 16) * 128 + col;
            union { __half h4[16]; uint4 v[2]; } U;
            #pragma unroll
            for (int i = 0; i < 16; i++)
                U.h4[i] = __float2half(stg[(rs * 16 + i) * 132 + col]);
            const size_t off = ((size_t)bidx * 1024 + colE) * 2048 + s0 + rs * 16;
            *(uint4*)(o3 + off)     = U.v[0];
            *(uint4*)(o3 + off + 8) = U.v[1];
        }
    }
}

// ---------------------------------------------------------------------------
// Input conversion: X, W_qkv, W_out -> single fp16, ONE launch
// ---------------------------------------------------------------------------
__global__ void conv_all(const float4* __restrict__ X,  __half* __restrict__ Xf, int n1,
                         const float4* __restrict__ Wq, __half* __restrict__ Wqf, int n2,
                         const float4* __restrict__ Wo, __half* __restrict__ Wof, int n3)
{
    int i = blockIdx.x * 256 + threadIdx.x;
    const float4* src; __half* dst;
    if (i < n1)            { src = X;  dst = Xf;  }
    else if (i < n1 + n2)  { src = Wq; dst = Wqf; i -= n1; }
    else if (i < n1+n2+n3) { src = Wo; dst = Wof; i -= n1 + n2; }
    else return;
    const float4 v = src[i];
    union { __half h[4]; uint2 u; } U;
    U.h[0] = __float2half(v.x); U.h[1] = __float2half(v.y);
    U.h[2] = __float2half(v.z); U.h[3] = __float2half(v.w);
    *(uint2*)(dst + (size_t)i * 4) = U.u;
}

// ---------------------------------------------------------------------------
extern "C" void kernel_launch(void* const* d_in, const int* in_sizes, int n_in,
                              void* d_out, int out_size)
{
    const float* X     = (const float*)d_in[0];
    const int*   mask  = (const int*)  d_in[1];
    const float* W_qkv = (const float*)d_in[2];
    const float* b_qkv = (const float*)d_in[3];
    const float* W_out = (const float*)d_in[4];
    const float* b_out = (const float*)d_in[5];
    float*       out   = (float*)d_out;

    __half *Xf, *Wqf, *Wof, *qf, *kf, *vtf, *E, *cf;
    float *rs;
    cudaGetSymbolAddress((void**)&Xf,   g_Xf);
    cudaGetSymbolAddress((void**)&Wqf,  g_Wqf);
    cudaGetSymbolAddress((void**)&Wof,  g_Wof);
    cudaGetSymbolAddress((void**)&qf,   g_qf);
    cudaGetSymbolAddress((void**)&kf,   g_kf);
    cudaGetSymbolAddress((void**)&vtf,  g_vtf);
    cudaGetSymbolAddress((void**)&E,    g_E);
    cudaGetSymbolAddress((void**)&rs,   g_rs);
    cudaGetSymbolAddress((void**)&cf,   g_cf);

    cudaFuncSetAttribute(hgemm_k<0>, cudaFuncAttributeMaxDynamicSharedMemorySize, HG_SMEM);
    cudaFuncSetAttribute(hgemm_k<1>, cudaFuncAttributeMaxDynamicSharedMemorySize, HG_SMEM);
    cudaFuncSetAttribute(hgemm_k<2>, cudaFuncAttributeMaxDynamicSharedMemorySize, HG_SMEM);
    cudaFuncSetAttribute(hgemm_k<3>, cudaFuncAttributeMaxDynamicSharedMemorySize, HG_SMEM);

    // Zero the rowsum accumulator (graph-capturable memset node)
    cudaMemsetAsync(rs, 0, (size_t)BATCH * SLEN * sizeof(float));

    // Convert inputs (single launch)
    {
        const int n1 = BATCH*SLEN*EMB/4, n2 = QKVF*EMB/4, n3 = EMB*EMB/4;
        conv_all<<<(n1 + n2 + n3 + 255)/256, 256>>>(
            (const float4*)X, Xf, n1,
            (const float4*)W_qkv, Wqf, n2,
            (const float4*)W_out, Wof, n3);
    }

    // 1) qkv = X @ W_qkv^T + b  -> q fp16, k fp16, V^T fp16
    hgemm_k<0><<<dim3(QKVF/128, (BATCH*SLEN)/128), 256, HG_SMEM>>>(
        Xf, Wqf, 0, EMB, 0, EMB, EMB, 1.0f,
        nullptr, 0, 0, qf, kf, vtf, b_qkv, nullptr, nullptr);

    // 2) E = mask ? exp(Q@K^T / 32) : 0  (fp16) + fused atomic row sums
    hgemm_k<1><<<dim3(SLEN/128, SLEN/128, BATCH), 256, HG_SMEM>>>(
        qf, kf, (size_t)SLEN*EMB, EMB, (size_t)SLEN*EMB, EMB, EMB, 0.03125f,
        nullptr, 0, 0, E, nullptr, nullptr, nullptr, mask, rs);

    // 3) ctx = (E @ V) * (1/rowsum)  -> ctx fp16
    hgemm_k<2><<<dim3(EMB/128, SLEN/128, BATCH), 256, HG_SMEM>>>(
        E, vtf, (size_t)SLEN*SLEN, SLEN, (size_t)EMB*SLEN, SLEN, SLEN, 1.0f,
        nullptr, 0, 0, cf, nullptr, nullptr, nullptr, nullptr, rs);

    // 4) out = ctx @ W_out^T + b  (fp32 out)
    hgemm_k<3><<<dim3(EMB/128, (BATCH*SLEN)/128), 256, HG_SMEM>>>(
        cf, Wof, 0, EMB, 0, EMB, EMB, 1.0f,
        out, 0, EMB, nullptr, nullptr, nullptr, b_out, nullptr, nullptr);
}